// round 1
// baseline (speedup 1.0000x reference)
#include <cuda_runtime.h>

#define NS 512
#define HH 256
#define WW 256
#define HW (HH * WW)
#define EPSF 1e-6f

// Per-stroke params: 3 x float4 per stroke
//  [0] = {C, S, u0=C*ox, v0=S*ox}
//  [1] = {oy, ia, ib, minq}
//  [2] = {w0, w1, w2, 0}
__device__ float4 g_sp[NS * 3];
__device__ float  g_partials[HH];   // one per pass-2 block (256 rows)

// ---------------------------------------------------------------------------
// Pass 1: per-stroke grid-min of quad + fold normalization into weights.
// One block per stroke, one thread per row. Row min of the convex 1-D parabola
// is at clamp(floor(vertex)) / clamp(floor(vertex)+1).
// ---------------------------------------------------------------------------
__global__ void __launch_bounds__(HH) pass1_kernel(
    const float* __restrict__ offset,
    const float* __restrict__ sigma,
    const float* __restrict__ theta,
    const float* __restrict__ color,
    const float* __restrict__ alpha)
{
    const int n = blockIdx.x;
    const int i = threadIdx.x;  // row

    const float ox = offset[2 * n + 0];
    const float oy = offset[2 * n + 1];
    const float sg0 = sigma[2 * n + 0];
    const float sg1 = sigma[2 * n + 1];
    const float th = theta[n];

    const float ratio = (float)WW / (float)HH;   // 1.0 here, keep general
    const float s0 = sg0 / ratio;
    float s, c;
    sincosf(th, &s, &c);
    const float ia = 0.5f / (s0 * s0);
    const float ib = 0.5f / (sg1 * sg1);

    const float hW = 1.0f / (float)WW;
    const float hH = 1.0f / (float)HH;

    const float y = (float)i * hH;
    const float dy = y - oy;
    const float u = fmaf(s, dy, c * ox);  // C*ox + S*dy
    const float v = fmaf(c, dy, s * ox);  // S*ox + C*dy
    const float P = c * hW;
    const float Q = s * hW;

    // quad(j) = ia*(P*j - u)^2 + ib*(Q*j - v)^2 ; vertex:
    const float al = ia * P * P + ib * Q * Q;          // > 0 always
    const float be = -2.0f * (ia * P * u + ib * Q * v);
    const float j0 = -be / (2.0f * al);
    const float jf = floorf(j0);
    const float j1 = fminf(fmaxf(jf, 0.0f), (float)(WW - 1));
    const float j2 = fminf(fmaxf(jf + 1.0f, 0.0f), (float)(WW - 1));

    float cx1 = fmaf(P, j1, -u), cy1 = fmaf(Q, j1, -v);
    float q1 = ia * cx1 * cx1 + ib * cy1 * cy1;
    float cx2 = fmaf(P, j2, -u), cy2 = fmaf(Q, j2, -v);
    float q2 = ia * cx2 * cx2 + ib * cy2 * cy2;
    float rowmin = fminf(q1, q2);

    // block-reduce min over 256 threads (8 warps)
    #pragma unroll
    for (int o = 16; o > 0; o >>= 1)
        rowmin = fminf(rowmin, __shfl_down_sync(0xffffffffu, rowmin, o));
    __shared__ float wmin[8];
    if ((i & 31) == 0) wmin[i >> 5] = rowmin;
    __syncthreads();

    if (i == 0) {
        float mq = wmin[0];
        #pragma unroll
        for (int k = 1; k < 8; k++) mq = fminf(mq, wmin[k]);

        const float maxpdf = expf(-mq);
        const float scale = maxpdf / (maxpdf + EPSF);
        const float a = alpha[n];
        const float w0 = a * color[3 * n + 0] * scale;
        const float w1 = a * color[3 * n + 1] * scale;
        const float w2 = a * color[3 * n + 2] * scale;

        g_sp[3 * n + 0] = make_float4(c, s, c * ox, s * ox);
        g_sp[3 * n + 1] = make_float4(oy, ia, ib, mq);
        g_sp[3 * n + 2] = make_float4(w0, w1, w2, 0.0f);
    }
}

// ---------------------------------------------------------------------------
// Pass 2: one block per row (256 rows), 128 threads, 2 pixels/thread.
// Shared cache of per-stroke params with row terms (U, V) pre-folded.
// Fused: stroke accumulation -> sigmoid -> output write -> sq-err partial sum.
// ---------------------------------------------------------------------------
__global__ void __launch_bounds__(128) pass2_kernel(
    const float* __restrict__ canvas,
    const float* __restrict__ target,
    float* __restrict__ out)
{
    __shared__ float4 sh[NS * 3];   // 24 KB

    const int row = blockIdx.x;
    const int tid = threadIdx.x;
    const float hW = 1.0f / (float)WW;
    const float hH = 1.0f / (float)HH;
    const float rowy = (float)row * hH;

    // Preload + fold per-row U,V
    for (int n = tid; n < NS; n += 128) {
        float4 b0 = g_sp[3 * n + 0];
        float4 b1 = g_sp[3 * n + 1];
        float4 b2 = g_sp[3 * n + 2];
        float dy = rowy - b1.x;
        float U = fmaf(b0.y, dy, b0.z);   // u0 + S*dy
        float V = fmaf(b0.x, dy, b0.w);   // v0 + C*dy
        sh[3 * n + 0] = make_float4(b0.x, b0.y, U, V);
        sh[3 * n + 1] = make_float4(b1.y, b1.z, b1.w, b2.x); // ia, ib, minq, w0
        sh[3 * n + 2] = make_float4(b2.y, b2.z, 0.0f, 0.0f); // w1, w2
    }
    __syncthreads();

    const int jA = tid;
    const int jB = tid + 128;
    const float xA = (float)jA * hW;
    const float xB = (float)jB * hW;

    float a00 = 0.f, a01 = 0.f, a02 = 0.f;  // pixel A: ch 0..2
    float a10 = 0.f, a11 = 0.f, a12 = 0.f;  // pixel B

    #pragma unroll 4
    for (int n = 0; n < NS; n++) {
        const float4 pa = sh[3 * n + 0];
        const float4 pb = sh[3 * n + 1];
        const float4 pc = sh[3 * n + 2];

        float cxA = fmaf(pa.x, xA, -pa.z);
        float cyA = fmaf(pa.y, xA, -pa.w);
        float mA = fmaf(-pb.x, cxA * cxA, fmaf(-pb.y, cyA * cyA, pb.z));
        float pA = __expf(mA);

        float cxB = fmaf(pa.x, xB, -pa.z);
        float cyB = fmaf(pa.y, xB, -pa.w);
        float mB = fmaf(-pb.x, cxB * cxB, fmaf(-pb.y, cyB * cyB, pb.z));
        float pB = __expf(mB);

        a00 = fmaf(pA, pb.w, a00);
        a01 = fmaf(pA, pc.x, a01);
        a02 = fmaf(pA, pc.y, a02);
        a10 = fmaf(pB, pb.w, a10);
        a11 = fmaf(pB, pc.x, a11);
        a12 = fmaf(pB, pc.y, a12);
    }

    // sigmoid + write + squared-error partial
    float sq = 0.0f;
    const int base = row * WW;
    float accA[3] = {a00, a01, a02};
    float accB[3] = {a10, a11, a12};
    #pragma unroll
    for (int ch = 0; ch < 3; ch++) {
        int idxA = ch * HW + base + jA;
        int idxB = ch * HW + base + jB;
        float zA = canvas[idxA] + accA[ch];
        float zB = canvas[idxB] + accB[ch];
        float oA = 1.0f / (1.0f + expf(-zA));
        float oB = 1.0f / (1.0f + expf(-zB));
        out[idxA] = oA;
        out[idxB] = oB;
        float dA = oA - target[idxA];
        float dB = oB - target[idxB];
        sq = fmaf(dA, dA, sq);
        sq = fmaf(dB, dB, sq);
    }

    // block reduce sq (4 warps)
    #pragma unroll
    for (int o = 16; o > 0; o >>= 1)
        sq += __shfl_down_sync(0xffffffffu, sq, o);
    __shared__ float wsum[4];
    if ((tid & 31) == 0) wsum[tid >> 5] = sq;
    __syncthreads();
    if (tid == 0)
        g_partials[row] = wsum[0] + wsum[1] + wsum[2] + wsum[3];
}

// ---------------------------------------------------------------------------
// Pass 3: finalize loss (single block).
// ---------------------------------------------------------------------------
__global__ void __launch_bounds__(NS) pass3_kernel(
    const float* __restrict__ sigma,
    const float* __restrict__ alpha,
    float* __restrict__ out,
    int out_size)
{
    const int t = threadIdx.x;  // 512
    __shared__ float sa[NS], sb[NS], sc[NS];

    sa[t] = (t < HH) ? g_partials[t] : 0.0f;
    sb[t] = fabsf(1.0f - sigma[2 * t + 0] / sigma[2 * t + 1]);
    sc[t] = fabsf(alpha[t]);
    __syncthreads();

    for (int s = NS / 2; s > 0; s >>= 1) {
        if (t < s) {
            sa[t] += sa[t + s];
            sb[t] += sb[t + s];
            sc[t] += sc[t + s];
        }
        __syncthreads();
    }

    if (t == 0) {
        float mse = sa[0] / (float)(3 * HW);
        float sharp = sb[0] * (0.001f / (float)NS);
        float transp = -sc[0] * (0.001f / (float)NS);
        float psnr = -10.0f * log10f(mse + 1e-12f);
        float loss = mse + transp + sharp - psnr / 30.0f;
        if (out_size > 3 * HW) out[3 * HW] = loss;
    }
}

// ---------------------------------------------------------------------------
extern "C" void kernel_launch(void* const* d_in, const int* in_sizes, int n_in,
                              void* d_out, int out_size)
{
    const float* canvas = (const float*)d_in[0];
    const float* target = (const float*)d_in[1];
    const float* offset = (const float*)d_in[2];
    const float* sigma  = (const float*)d_in[3];
    const float* theta  = (const float*)d_in[4];
    const float* color  = (const float*)d_in[5];
    const float* alpha  = (const float*)d_in[6];
    float* out = (float*)d_out;

    pass1_kernel<<<NS, HH>>>(offset, sigma, theta, color, alpha);
    pass2_kernel<<<HH, 128>>>(canvas, target, out);
    pass3_kernel<<<1, NS>>>(sigma, alpha, out, out_size);
}

// round 2
// speedup vs baseline: 1.3269x; 1.3269x over previous
#include <cuda_runtime.h>

#define NS 512
#define HH 256
#define WW 256
#define HW (HH * WW)
#define EPSF 1e-6f
#define L2E 1.4426950408889634f

typedef unsigned long long u64;

// Per-stroke params (new layout):
//  g_p0[n] = {aL, bL0, bL1, oy}      a = aL (row-indep); b(row) = bL0 + bL1*dy
//  g_p1[n] = {cL0, cL1, cL2, w0}     c(row) = cL0 + cL1*dy + cL2*dy^2
//  g_p2[n] = {w1, w2, 0, 0}
// where m(x) = a*x^2 + b*x + c is log2 of normalized pdf (<= ~0), pdf = ex2(m)
__device__ float4 g_p0[NS];
__device__ float4 g_p1[NS];
__device__ float4 g_p2[NS];
__device__ float  g_partials[1024];

// ---- packed f32x2 helpers -------------------------------------------------
__device__ __forceinline__ u64 ffma2(u64 a, u64 b, u64 c) {
    u64 d;
    asm("fma.rn.f32x2 %0, %1, %2, %3;" : "=l"(d) : "l"(a), "l"(b), "l"(c));
    return d;
}
__device__ __forceinline__ u64 pack2(float lo, float hi) {
    u64 d;
    asm("mov.b64 %0, {%1, %2};" : "=l"(d) : "f"(lo), "f"(hi));
    return d;
}
__device__ __forceinline__ void unpack2(u64 v, float& lo, float& hi) {
    asm("mov.b64 {%0, %1}, %2;" : "=f"(lo), "=f"(hi) : "l"(v));
}
__device__ __forceinline__ float ex2f(float x) {
    float r;
    asm("ex2.approx.ftz.f32 %0, %1;" : "=f"(r) : "f"(x));
    return r;
}
__device__ __forceinline__ void lds_v2u64(unsigned addr, u64& a, u64& b) {
    asm("ld.shared.v2.u64 {%0, %1}, [%2];" : "=l"(a), "=l"(b) : "r"(addr));
}

// ---------------------------------------------------------------------------
// Pass 1: warp per stroke. Each lane evaluates row-min of the convex parabola
// for 8 rows (vertex clamp trick), warp shfl-min reduce, lane 0 emits the
// per-stroke polynomial coefficients + normalized weights.
// grid = 64, block = 256 (8 warps = 8 strokes per block)
// ---------------------------------------------------------------------------
__global__ void __launch_bounds__(256) pass1_kernel(
    const float* __restrict__ offset,
    const float* __restrict__ sigma,
    const float* __restrict__ theta,
    const float* __restrict__ color,
    const float* __restrict__ alpha)
{
    const int tid = threadIdx.x;
    const int n = blockIdx.x * 8 + (tid >> 5);
    const int lane = tid & 31;

    const float ox = offset[2 * n + 0];
    const float oy = offset[2 * n + 1];
    const float sg0 = sigma[2 * n + 0];
    const float sg1 = sigma[2 * n + 1];
    const float th = theta[n];

    const float ratio = (float)WW / (float)HH;
    const float s0 = sg0 / ratio;
    float s, c;
    sincosf(th, &s, &c);
    const float ia = 0.5f / (s0 * s0);
    const float ib = 0.5f / (sg1 * sg1);

    const float hW = 1.0f / (float)WW;
    const float hH = 1.0f / (float)HH;
    const float u0 = c * ox;
    const float v0 = s * ox;
    const float P = c * hW;
    const float Q = s * hW;
    const float al = ia * P * P + ib * Q * Q;   // row-independent, > 0
    const float inv2al = 0.5f / al;

    float rowmin = 3.4e38f;
    #pragma unroll
    for (int k = 0; k < 8; k++) {
        const int i = lane + 32 * k;
        const float dy = (float)i * hH - oy;
        const float u = fmaf(s, dy, u0);
        const float v = fmaf(c, dy, v0);
        const float be = -2.0f * (ia * P * u + ib * Q * v);
        const float j0 = -be * inv2al;
        const float jf = floorf(j0);
        const float j1 = fminf(fmaxf(jf, 0.0f), (float)(WW - 1));
        const float j2 = fminf(fmaxf(jf + 1.0f, 0.0f), (float)(WW - 1));
        float cx1 = fmaf(P, j1, -u), cy1 = fmaf(Q, j1, -v);
        float q1 = ia * cx1 * cx1 + ib * cy1 * cy1;
        float cx2 = fmaf(P, j2, -u), cy2 = fmaf(Q, j2, -v);
        float q2 = ia * cx2 * cx2 + ib * cy2 * cy2;
        rowmin = fminf(rowmin, fminf(q1, q2));
    }
    #pragma unroll
    for (int o = 16; o > 0; o >>= 1)
        rowmin = fminf(rowmin, __shfl_down_sync(0xffffffffu, rowmin, o));

    if (lane == 0) {
        const float mq = rowmin;
        const float maxpdf = expf(-mq);
        const float scale = maxpdf / (maxpdf + EPSF);
        const float a = alpha[n];
        const float w0 = a * color[3 * n + 0] * scale;
        const float w1 = a * color[3 * n + 1] * scale;
        const float w2 = a * color[3 * n + 2] * scale;

        // quad(x,dy) = A'x^2 + B'(dy)x + C'(dy), x in [0,1)
        const float Ap = ia * c * c + ib * s * s;
        const float B0 = -2.0f * (ia * c * u0 + ib * s * v0);
        const float B1 = -2.0f * s * c * (ia + ib);
        const float C0 = ia * u0 * u0 + ib * v0 * v0;
        const float C1 = 2.0f * (ia * u0 * s + ib * v0 * c);
        const float C2 = ia * s * s + ib * c * c;

        g_p0[n] = make_float4(-L2E * Ap, -L2E * B0, -L2E * B1, oy);
        g_p1[n] = make_float4(L2E * (mq - C0), -L2E * C1, -L2E * C2, w0);
        g_p2[n] = make_float4(w1, w2, 0.0f, 0.0f);
    }
}

// ---------------------------------------------------------------------------
// Pass 2: one block per quarter-row. 64 threads, 1 pixel each.
// Strokes processed in PAIRS via packed f32x2 FFMA2: the two halves of each
// 64-bit operand are stroke 2p and 2p+1. Shared layout (12 KB):
//   [p*16 + 0..15]        = {aE,aO, bE,bO}
//   [4096 + p*16 + 0..15] = {cE,cO, w0E,w0O}
//   [8192 + p*16 + 0..15] = {w1E,w1O, w2E,w2O}
// Fused epilogue: sigmoid + out write + sq-err partial.
// ---------------------------------------------------------------------------
__global__ void __launch_bounds__(64) pass2_kernel(
    const float* __restrict__ canvas,
    const float* __restrict__ target,
    float* __restrict__ out)
{
    __shared__ float sh[3072];   // 12 KB

    const int tid = threadIdx.x;
    const int row = blockIdx.x >> 2;
    const int j = ((blockIdx.x & 3) << 6) + tid;
    const float hW = 1.0f / (float)WW;
    const float hH = 1.0f / (float)HH;
    const float rowy = (float)row * hH;
    const float x = (float)j * hW;

    // Preload: fold per-row dy into b, c coefficients; scatter into pair slots
    for (int n = tid; n < NS; n += 64) {
        float4 p0 = g_p0[n];
        float4 p1 = g_p1[n];
        float4 p2 = g_p2[n];
        float dy = rowy - p0.w;
        float b = fmaf(p0.z, dy, p0.y);
        float cc = fmaf(fmaf(p1.z, dy, p1.y), dy, p1.x);
        int p = n >> 1, h = n & 1;
        sh[p * 4 + h] = p0.x;              // a
        sh[p * 4 + 2 + h] = b;
        sh[1024 + p * 4 + h] = cc;
        sh[1024 + p * 4 + 2 + h] = p1.w;   // w0
        sh[2048 + p * 4 + h] = p2.x;       // w1
        sh[2048 + p * 4 + 2 + h] = p2.y;   // w2
    }
    __syncthreads();

    const unsigned sbase = (unsigned)__cvta_generic_to_shared(sh);
    const u64 xx = pack2(x, x);
    u64 acc0 = pack2(0.0f, 0.0f);
    u64 acc1 = acc0, acc2 = acc0;

    #pragma unroll 4
    for (int p = 0; p < NS / 2; p++) {
        u64 aa, bb, cc, w0, w1, w2;
        lds_v2u64(sbase + p * 16, aa, bb);
        lds_v2u64(sbase + 4096 + p * 16, cc, w0);
        lds_v2u64(sbase + 8192 + p * 16, w1, w2);
        u64 t = ffma2(aa, xx, bb);
        u64 m = ffma2(t, xx, cc);
        float mE, mO;
        unpack2(m, mE, mO);
        u64 pp = pack2(ex2f(mE), ex2f(mO));
        acc0 = ffma2(pp, w0, acc0);
        acc1 = ffma2(pp, w1, acc1);
        acc2 = ffma2(pp, w2, acc2);
    }

    float e, o, ch0, ch1, ch2;
    unpack2(acc0, e, o); ch0 = e + o;
    unpack2(acc1, e, o); ch1 = e + o;
    unpack2(acc2, e, o); ch2 = e + o;

    float sq = 0.0f;
    const int base = row * WW + j;
    float chv[3] = {ch0, ch1, ch2};
    #pragma unroll
    for (int ch = 0; ch < 3; ch++) {
        int idx = ch * HW + base;
        float z = canvas[idx] + chv[ch];
        float ov = 1.0f / (1.0f + __expf(-z));
        out[idx] = ov;
        float d = ov - target[idx];
        sq = fmaf(d, d, sq);
    }

    #pragma unroll
    for (int o2 = 16; o2 > 0; o2 >>= 1)
        sq += __shfl_down_sync(0xffffffffu, sq, o2);
    __shared__ float ws[2];
    if ((tid & 31) == 0) ws[tid >> 5] = sq;
    __syncthreads();
    if (tid == 0) g_partials[blockIdx.x] = ws[0] + ws[1];
}

// ---------------------------------------------------------------------------
// Pass 3: finalize loss (single block, 512 threads; 1024 partials).
// ---------------------------------------------------------------------------
__global__ void __launch_bounds__(NS) pass3_kernel(
    const float* __restrict__ sigma,
    const float* __restrict__ alpha,
    float* __restrict__ out,
    int out_size)
{
    const int t = threadIdx.x;
    __shared__ float sa[NS], sb[NS], sc[NS];

    sa[t] = g_partials[t] + g_partials[t + 512];
    sb[t] = fabsf(1.0f - sigma[2 * t + 0] / sigma[2 * t + 1]);
    sc[t] = fabsf(alpha[t]);
    __syncthreads();

    for (int s = NS / 2; s > 0; s >>= 1) {
        if (t < s) {
            sa[t] += sa[t + s];
            sb[t] += sb[t + s];
            sc[t] += sc[t + s];
        }
        __syncthreads();
    }

    if (t == 0) {
        float mse = sa[0] / (float)(3 * HW);
        float sharp = sb[0] * (0.001f / (float)NS);
        float transp = -sc[0] * (0.001f / (float)NS);
        float psnr = -10.0f * log10f(mse + 1e-12f);
        float loss = mse + transp + sharp - psnr / 30.0f;
        if (out_size > 3 * HW) out[3 * HW] = loss;
    }
}

// ---------------------------------------------------------------------------
extern "C" void kernel_launch(void* const* d_in, const int* in_sizes, int n_in,
                              void* d_out, int out_size)
{
    const float* canvas = (const float*)d_in[0];
    const float* target = (const float*)d_in[1];
    const float* offset = (const float*)d_in[2];
    const float* sigma  = (const float*)d_in[3];
    const float* theta  = (const float*)d_in[4];
    const float* color  = (const float*)d_in[5];
    const float* alpha  = (const float*)d_in[6];
    float* out = (float*)d_out;

    pass1_kernel<<<64, 256>>>(offset, sigma, theta, color, alpha);
    pass2_kernel<<<1024, 64>>>(canvas, target, out);
    pass3_kernel<<<1, 512>>>(sigma, alpha, out, out_size);
}

// round 3
// speedup vs baseline: 1.4431x; 1.0875x over previous
#include <cuda_runtime.h>

#define NS 512
#define HH 256
#define WW 256
#define HW (HH * WW)
#define EPSF 1e-6f
#define L2E 1.4426950408889634f

typedef unsigned long long u64;

// Per-stroke params:
//  g_p0[n] = {aL, bL0, bL1, oy}      a row-indep; b(row) = bL0 + bL1*dy
//  g_p1[n] = {cL0, cL1, cL2, w0}     c(row) = cL0 + cL1*dy + cL2*dy^2
//  g_p2[n] = {w1, w2, 0, 0}
// m(x) = a*x^2 + b*x + c = log2(normalized pdf), pdf = ex2(m)
__device__ float4 g_p0[NS];
__device__ float4 g_p1[NS];
__device__ float4 g_p2[NS];
__device__ float  g_partials[512];
__device__ unsigned g_done;

// ---- packed f32x2 helpers -------------------------------------------------
__device__ __forceinline__ u64 ffma2(u64 a, u64 b, u64 c) {
    u64 d;
    asm("fma.rn.f32x2 %0, %1, %2, %3;" : "=l"(d) : "l"(a), "l"(b), "l"(c));
    return d;
}
__device__ __forceinline__ u64 pack2(float lo, float hi) {
    u64 d;
    asm("mov.b64 %0, {%1, %2};" : "=l"(d) : "f"(lo), "f"(hi));
    return d;
}
__device__ __forceinline__ void unpack2(u64 v, float& lo, float& hi) {
    asm("mov.b64 {%0, %1}, %2;" : "=f"(lo), "=f"(hi) : "l"(v));
}
__device__ __forceinline__ float ex2f(float x) {
    float r;
    asm("ex2.approx.ftz.f32 %0, %1;" : "=f"(r) : "f"(x));
    return r;
}
__device__ __forceinline__ void lds_v2u64(unsigned addr, u64& a, u64& b) {
    asm("ld.shared.v2.u64 {%0, %1}, [%2];" : "=l"(a), "=l"(b) : "r"(addr));
}

// ---------------------------------------------------------------------------
// Pass 1: ONE THREAD PER STROKE. Closed-form min of the PD quadratic over the
// pixel rectangle (interior + 4 clamped edge minima), then exact grid-min
// refinement on a 4x4 neighborhood of the continuous argmin.
// ---------------------------------------------------------------------------
__global__ void __launch_bounds__(256) pass1_kernel(
    const float* __restrict__ offset,
    const float* __restrict__ sigma,
    const float* __restrict__ theta,
    const float* __restrict__ color,
    const float* __restrict__ alpha)
{
    const int n = blockIdx.x * 256 + threadIdx.x;
    if (n == 0) g_done = 0;
    if (n >= NS) return;

    const float ox = offset[2 * n + 0];
    const float oy = offset[2 * n + 1];
    const float sg0 = sigma[2 * n + 0];
    const float sg1 = sigma[2 * n + 1];
    const float th = theta[n];

    const float ratio = (float)WW / (float)HH;
    const float s0 = sg0 / ratio;
    float s, c;
    __sincosf(th, &s, &c);
    const float ia = __fdividef(0.5f, s0 * s0);
    const float ib = __fdividef(0.5f, sg1 * sg1);

    // quad(dx,dy) = A dx^2 + B dx dy + C dy^2, dx = x-ox, dy = y-oy
    const float A = ia * c * c + ib * s * s;
    const float C = ia * s * s + ib * c * c;
    const float B = -2.0f * s * c * (ia + ib);

    const float Xm = (float)(WW - 1) / (float)WW;
    const float Ym = (float)(HH - 1) / (float)HH;
    const float x0d = -ox, x1d = Xm - ox;
    const float y0d = -oy, y1d = Ym - oy;

    float best = 3.4e38f, bdx = 0.0f, bdy = 0.0f;
    if (x0d <= 0.0f && x1d >= 0.0f && y0d <= 0.0f && y1d >= 0.0f) {
        best = 0.0f; bdx = 0.0f; bdy = 0.0f;
    }
    const float i2A = __fdividef(-0.5f, A);
    const float i2C = __fdividef(-0.5f, C);
    // edges dx = x0d / x1d
    #pragma unroll
    for (int e = 0; e < 2; e++) {
        float ex = e ? x1d : x0d;
        float dy = fminf(fmaxf(B * ex * i2C, y0d), y1d);
        float q = fmaf(A * ex, ex, fmaf(B * ex, dy, C * dy * dy));
        if (q < best) { best = q; bdx = ex; bdy = dy; }
    }
    // edges dy = y0d / y1d
    #pragma unroll
    for (int e = 0; e < 2; e++) {
        float ey = e ? y1d : y0d;
        float dx = fminf(fmaxf(B * ey * i2A, x0d), x1d);
        float q = fmaf(A * dx, dx, fmaf(B * dx, ey, C * ey * ey));
        if (q < best) { best = q; bdx = dx; bdy = ey; }
    }

    // exact grid min on 4x4 neighborhood of continuous argmin
    const float jx = floorf((bdx + ox) * (float)WW) - 1.0f;
    const float iy = floorf((bdy + oy) * (float)HH) - 1.0f;
    float mq = 3.4e38f;
    #pragma unroll
    for (int a2 = 0; a2 < 4; a2++) {
        float jj = fminf(fmaxf(jx + (float)a2, 0.0f), (float)(WW - 1));
        float dx = jj * (1.0f / (float)WW) - ox;
        #pragma unroll
        for (int b2 = 0; b2 < 4; b2++) {
            float ii = fminf(fmaxf(iy + (float)b2, 0.0f), (float)(HH - 1));
            float dy = ii * (1.0f / (float)HH) - oy;
            float q = fmaf(A * dx, dx, fmaf(B * dx, dy, C * dy * dy));
            mq = fminf(mq, q);
        }
    }

    const float maxpdf = __expf(-mq);
    const float scale = __fdividef(maxpdf, maxpdf + EPSF);
    const float al = alpha[n];
    const float w0 = al * color[3 * n + 0] * scale;
    const float w1 = al * color[3 * n + 1] * scale;
    const float w2 = al * color[3 * n + 2] * scale;

    // polynomial in absolute x: quad = A x^2 + (B0+B1 dy) x + (C0+C1 dy+C2 dy^2)
    const float B0 = -2.0f * A * ox;
    const float B1 = B;
    const float C0 = A * ox * ox;
    const float C1 = -B * ox;
    const float C2 = C;

    g_p0[n] = make_float4(-L2E * A, -L2E * B0, -L2E * B1, oy);
    g_p1[n] = make_float4(L2E * (mq - C0), -L2E * C1, -L2E * C2, w0);
    g_p2[n] = make_float4(w1, w2, 0.0f, 0.0f);
}

// ---------------------------------------------------------------------------
// Pass 2: 512 blocks x 128 threads, half-row per block, 1 px/thread.
// Stroke-pair f32x2 inner loop; fused sigmoid + out + sq-err; LAST block
// computes the full loss (pass3 fused).
// ---------------------------------------------------------------------------
__global__ void __launch_bounds__(128) pass2_kernel(
    const float* __restrict__ canvas,
    const float* __restrict__ target,
    const float* __restrict__ sigma,
    const float* __restrict__ alpha,
    float* __restrict__ out,
    int out_size)
{
    __shared__ float sh[3072];   // 12 KB
    __shared__ float ws[4];
    __shared__ int lastflag;

    const int tid = threadIdx.x;
    const int bid = blockIdx.x;
    const int row = bid >> 1;
    const int j = ((bid & 1) << 7) + tid;
    const float hW = 1.0f / (float)WW;
    const float hH = 1.0f / (float)HH;
    const float rowy = (float)row * hH;
    const float x = (float)j * hW;

    // preload + fold per-row dy
    for (int n = tid; n < NS; n += 128) {
        float4 p0 = g_p0[n];
        float4 p1 = g_p1[n];
        float4 p2 = g_p2[n];
        float dy = rowy - p0.w;
        float b = fmaf(p0.z, dy, p0.y);
        float cc = fmaf(fmaf(p1.z, dy, p1.y), dy, p1.x);
        int p = n >> 1, h = n & 1;
        sh[p * 4 + h] = p0.x;
        sh[p * 4 + 2 + h] = b;
        sh[1024 + p * 4 + h] = cc;
        sh[1024 + p * 4 + 2 + h] = p1.w;
        sh[2048 + p * 4 + h] = p2.x;
        sh[2048 + p * 4 + 2 + h] = p2.y;
    }
    __syncthreads();

    const unsigned sbase = (unsigned)__cvta_generic_to_shared(sh);
    const u64 xx = pack2(x, x);
    u64 acc0 = pack2(0.0f, 0.0f);
    u64 acc1 = acc0, acc2 = acc0;

    #pragma unroll 4
    for (int p = 0; p < NS / 2; p++) {
        u64 aa, bb, cc, w0, w1, w2;
        lds_v2u64(sbase + p * 16, aa, bb);
        lds_v2u64(sbase + 4096 + p * 16, cc, w0);
        lds_v2u64(sbase + 8192 + p * 16, w1, w2);
        u64 t = ffma2(aa, xx, bb);
        u64 m = ffma2(t, xx, cc);
        float mE, mO;
        unpack2(m, mE, mO);
        u64 pp = pack2(ex2f(mE), ex2f(mO));
        acc0 = ffma2(pp, w0, acc0);
        acc1 = ffma2(pp, w1, acc1);
        acc2 = ffma2(pp, w2, acc2);
    }

    float e, o, ch0, ch1, ch2;
    unpack2(acc0, e, o); ch0 = e + o;
    unpack2(acc1, e, o); ch1 = e + o;
    unpack2(acc2, e, o); ch2 = e + o;

    float sq = 0.0f;
    const int base = row * WW + j;
    float chv[3] = {ch0, ch1, ch2};
    #pragma unroll
    for (int ch = 0; ch < 3; ch++) {
        int idx = ch * HW + base;
        float z = canvas[idx] + chv[ch];
        float ov = __fdividef(1.0f, 1.0f + __expf(-z));
        out[idx] = ov;
        float d = ov - target[idx];
        sq = fmaf(d, d, sq);
    }

    #pragma unroll
    for (int o2 = 16; o2 > 0; o2 >>= 1)
        sq += __shfl_down_sync(0xffffffffu, sq, o2);
    if ((tid & 31) == 0) ws[tid >> 5] = sq;
    __syncthreads();
    if (tid == 0) {
        g_partials[bid] = ws[0] + ws[1] + ws[2] + ws[3];
        __threadfence();
        unsigned prev = atomicAdd(&g_done, 1u);
        lastflag = (prev == 511u) ? 1 : 0;
    }
    __syncthreads();

    if (lastflag) {
        // final loss reduction (deterministic fixed shape)
        __shared__ float sa[128], sb[128], sc2[128];
        float pa = 0.f, pb = 0.f, pc = 0.f;
        #pragma unroll
        for (int k = 0; k < 4; k++) {
            pa += g_partials[tid + 128 * k];
            int nn = tid + 128 * k;
            pb += fabsf(1.0f - __fdividef(sigma[2 * nn], sigma[2 * nn + 1]));
            pc += fabsf(alpha[nn]);
        }
        sa[tid] = pa; sb[tid] = pb; sc2[tid] = pc;
        __syncthreads();
        for (int s2 = 64; s2 > 0; s2 >>= 1) {
            if (tid < s2) {
                sa[tid] += sa[tid + s2];
                sb[tid] += sb[tid + s2];
                sc2[tid] += sc2[tid + s2];
            }
            __syncthreads();
        }
        if (tid == 0) {
            float mse = sa[0] / (float)(3 * HW);
            float sharp = sb[0] * (0.001f / (float)NS);
            float transp = -sc2[0] * (0.001f / (float)NS);
            float psnr = -10.0f * log10f(mse + 1e-12f);
            float loss = mse + transp + sharp - psnr / 30.0f;
            if (out_size > 3 * HW) out[3 * HW] = loss;
        }
    }
}

// ---------------------------------------------------------------------------
extern "C" void kernel_launch(void* const* d_in, const int* in_sizes, int n_in,
                              void* d_out, int out_size)
{
    const float* canvas = (const float*)d_in[0];
    const float* target = (const float*)d_in[1];
    const float* offset = (const float*)d_in[2];
    const float* sigma  = (const float*)d_in[3];
    const float* theta  = (const float*)d_in[4];
    const float* color  = (const float*)d_in[5];
    const float* alpha  = (const float*)d_in[6];
    float* out = (float*)d_out;

    pass1_kernel<<<2, 256>>>(offset, sigma, theta, color, alpha);
    pass2_kernel<<<512, 128>>>(canvas, target, sigma, alpha, out, out_size);
}

// round 4
// speedup vs baseline: 1.5438x; 1.0698x over previous
#include <cuda_runtime.h>

#define NS 512
#define HH 256
#define WW 256
#define HW (HH * WW)
#define NG 8            // stroke groups
#define GS (NS / NG)    // strokes per group = 64
#define EPSF 1e-6f
#define L2E 1.4426950408889634f
#define HPX (1.0f / 256.0f)

typedef unsigned long long u64;

// Per-stroke params from pass1 (log2 domain, sign folded):
//  g_p0[n] = {a, B0, B1, oy}   m(x,dy) = a x^2 + (B0+B1 dy) x + (C0+C1 dy+C2 dy^2)
//  g_p1[n] = {C0', C1, C2, w0} (C0' includes +L2E*mq normalization)
//  g_p2[n] = {w1, w2, K, 0}    K = 2^(2 a h^2)  (per-pixel-step ratio of ratios)
__device__ float4 g_p0[NS];
__device__ float4 g_p1[NS];
__device__ float4 g_p2[NS];
__device__ float  g_part[NG][3 * HW];   // per-group partial stroke sums
__device__ float  g_red[192];
__device__ unsigned g_done;

__device__ __forceinline__ u64 ffma2(u64 a, u64 b, u64 c) {
    u64 d;
    asm("fma.rn.f32x2 %0, %1, %2, %3;" : "=l"(d) : "l"(a), "l"(b), "l"(c));
    return d;
}
__device__ __forceinline__ u64 pack2(float lo, float hi) {
    u64 d;
    asm("mov.b64 %0, {%1, %2};" : "=l"(d) : "f"(lo), "f"(hi));
    return d;
}
__device__ __forceinline__ void unpack2(u64 v, float& lo, float& hi) {
    asm("mov.b64 {%0, %1}, %2;" : "=f"(lo), "=f"(hi) : "l"(v));
}
__device__ __forceinline__ float ex2f(float x) {
    float r;
    asm("ex2.approx.ftz.f32 %0, %1;" : "=f"(r) : "f"(x));
    return r;
}
__device__ __forceinline__ void lds_v4f(unsigned addr, float4& v) {
    asm("ld.shared.v4.f32 {%0, %1, %2, %3}, [%4];"
        : "=f"(v.x), "=f"(v.y), "=f"(v.z), "=f"(v.w) : "r"(addr));
}

// ---------------------------------------------------------------------------
// Pass 1: one thread per stroke; closed-form rect min + 4x4 grid refinement.
// ---------------------------------------------------------------------------
__global__ void __launch_bounds__(256) pass1_kernel(
    const float* __restrict__ offset,
    const float* __restrict__ sigma,
    const float* __restrict__ theta,
    const float* __restrict__ color,
    const float* __restrict__ alpha)
{
    const int n = blockIdx.x * 256 + threadIdx.x;
    if (n == 0) g_done = 0;
    if (n >= NS) return;

    const float ox = offset[2 * n + 0];
    const float oy = offset[2 * n + 1];
    const float sg0 = sigma[2 * n + 0];
    const float sg1 = sigma[2 * n + 1];
    const float th = theta[n];

    const float ratio = (float)WW / (float)HH;
    const float s0 = sg0 / ratio;
    float s, c;
    __sincosf(th, &s, &c);
    const float ia = __fdividef(0.5f, s0 * s0);
    const float ib = __fdividef(0.5f, sg1 * sg1);

    const float A = ia * c * c + ib * s * s;
    const float C = ia * s * s + ib * c * c;
    const float B = -2.0f * s * c * (ia + ib);

    const float Xm = (float)(WW - 1) / (float)WW;
    const float Ym = (float)(HH - 1) / (float)HH;
    const float x0d = -ox, x1d = Xm - ox;
    const float y0d = -oy, y1d = Ym - oy;

    float best = 3.4e38f, bdx = 0.0f, bdy = 0.0f;
    if (x0d <= 0.0f && x1d >= 0.0f && y0d <= 0.0f && y1d >= 0.0f) {
        best = 0.0f; bdx = 0.0f; bdy = 0.0f;
    }
    const float i2A = __fdividef(-0.5f, A);
    const float i2C = __fdividef(-0.5f, C);
    #pragma unroll
    for (int e = 0; e < 2; e++) {
        float ex = e ? x1d : x0d;
        float dy = fminf(fmaxf(B * ex * i2C, y0d), y1d);
        float q = fmaf(A * ex, ex, fmaf(B * ex, dy, C * dy * dy));
        if (q < best) { best = q; bdx = ex; bdy = dy; }
    }
    #pragma unroll
    for (int e = 0; e < 2; e++) {
        float ey = e ? y1d : y0d;
        float dx = fminf(fmaxf(B * ey * i2A, x0d), x1d);
        float q = fmaf(A * dx, dx, fmaf(B * dx, ey, C * ey * ey));
        if (q < best) { best = q; bdx = dx; bdy = ey; }
    }

    const float jx = floorf((bdx + ox) * (float)WW) - 1.0f;
    const float iy = floorf((bdy + oy) * (float)HH) - 1.0f;
    float mq = 3.4e38f;
    #pragma unroll
    for (int a2 = 0; a2 < 4; a2++) {
        float jj = fminf(fmaxf(jx + (float)a2, 0.0f), (float)(WW - 1));
        float dx = jj * (1.0f / (float)WW) - ox;
        #pragma unroll
        for (int b2 = 0; b2 < 4; b2++) {
            float ii = fminf(fmaxf(iy + (float)b2, 0.0f), (float)(HH - 1));
            float dy = ii * (1.0f / (float)HH) - oy;
            float q = fmaf(A * dx, dx, fmaf(B * dx, dy, C * dy * dy));
            mq = fminf(mq, q);
        }
    }

    const float maxpdf = __expf(-mq);
    const float scale = __fdividef(maxpdf, maxpdf + EPSF);
    const float al = alpha[n];
    const float w0 = al * color[3 * n + 0] * scale;
    const float w1 = al * color[3 * n + 1] * scale;
    const float w2 = al * color[3 * n + 2] * scale;

    const float a = -L2E * A;
    const float B0 = -2.0f * A * ox;
    const float C0 = A * ox * ox;
    const float C1 = -B * ox;
    const float K = exp2f(2.0f * a * HPX * HPX);

    g_p0[n] = make_float4(a, -L2E * B0, -L2E * B, oy);
    g_p1[n] = make_float4(L2E * (mq - C0), -L2E * C1, -L2E * C, w0);
    g_p2[n] = make_float4(w1, w2, K, 0.0f);
}

// ---------------------------------------------------------------------------
// Pass 2: 2048 blocks x 32 threads. block = (row, stroke-group). Each thread
// owns 8 contiguous pixels; per stroke: 2 LDS.128 -> 2 EX2 anchors ->
// multiplicative chain -> packed f32x2 accumulation. Writes per-group partial.
// ---------------------------------------------------------------------------
__global__ void __launch_bounds__(32) pass2_kernel()
{
    __shared__ float sh[GS * 8];   // 2 KB

    const int tid = threadIdx.x;
    const int g = blockIdx.x & (NG - 1);
    const int row = blockIdx.x >> 3;
    const float rowy = (float)row * HPX;

    // preload + row-fold 64 strokes (2 per thread)
    #pragma unroll
    for (int k = 0; k < 2; k++) {
        int sl = tid + 32 * k;
        int n = g * GS + sl;
        float4 p0 = g_p0[n];
        float4 p1 = g_p1[n];
        float4 p2 = g_p2[n];
        float dy = rowy - p0.w;
        float b = fmaf(p0.z, dy, p0.y);
        float cc = fmaf(fmaf(p1.z, dy, p1.y), dy, p1.x);
        float* d = &sh[sl * 8];
        d[0] = p0.x;          // a
        d[1] = b;
        d[2] = cc;
        d[3] = b * HPX;       // bh
        d[4] = p2.z;          // K
        d[5] = p1.w;          // w0
        d[6] = p2.x;          // w1
        d[7] = p2.y;          // w2
    }
    __syncthreads();

    const float x0 = (float)(tid * 8) * HPX;
    const float X1c = fmaf(2.0f * HPX, x0, HPX * HPX);  // 2h x0 + h^2

    u64 acc[3][4];
    #pragma unroll
    for (int ch = 0; ch < 3; ch++)
        #pragma unroll
        for (int k = 0; k < 4; k++) acc[ch][k] = 0ull;

    const unsigned sbase = (unsigned)__cvta_generic_to_shared(sh);

    #pragma unroll 2
    for (int sl = 0; sl < GS; sl++) {
        float4 q0, q1;
        lds_v4f(sbase + sl * 32, q0);
        lds_v4f(sbase + sl * 32 + 16, q1);
        const float a = q0.x, b = q0.y, cc = q0.z, bh = q0.w;
        const float K = q1.x;

        float m0 = fmaf(fmaf(a, x0, b), x0, cc);
        float d0 = fmaf(a, X1c, bh);
        float p0 = ex2f(m0);
        float t = ex2f(d0);
        float p1 = p0 * t; t *= K;
        float p2 = p1 * t; t *= K;
        float p3 = p2 * t; t *= K;
        float p4 = p3 * t; t *= K;
        float p5 = p4 * t; t *= K;
        float p6 = p5 * t; t *= K;
        float p7 = p6 * t;

        u64 pk0 = pack2(p0, p1);
        u64 pk1 = pack2(p2, p3);
        u64 pk2 = pack2(p4, p5);
        u64 pk3 = pack2(p6, p7);
        u64 ww0 = pack2(q1.y, q1.y);
        u64 ww1 = pack2(q1.z, q1.z);
        u64 ww2 = pack2(q1.w, q1.w);

        acc[0][0] = ffma2(pk0, ww0, acc[0][0]);
        acc[0][1] = ffma2(pk1, ww0, acc[0][1]);
        acc[0][2] = ffma2(pk2, ww0, acc[0][2]);
        acc[0][3] = ffma2(pk3, ww0, acc[0][3]);
        acc[1][0] = ffma2(pk0, ww1, acc[1][0]);
        acc[1][1] = ffma2(pk1, ww1, acc[1][1]);
        acc[1][2] = ffma2(pk2, ww1, acc[1][2]);
        acc[1][3] = ffma2(pk3, ww1, acc[1][3]);
        acc[2][0] = ffma2(pk0, ww2, acc[2][0]);
        acc[2][1] = ffma2(pk1, ww2, acc[2][1]);
        acc[2][2] = ffma2(pk2, ww2, acc[2][2]);
        acc[2][3] = ffma2(pk3, ww2, acc[2][3]);
    }

    // write 8 px x 3 ch partial (two float4 per channel)
    const int base = row * WW + tid * 8;
    #pragma unroll
    for (int ch = 0; ch < 3; ch++) {
        float4* dst = (float4*)&g_part[g][ch * HW + base];
        float lo0, hi0, lo1, hi1;
        unpack2(acc[ch][0], lo0, hi0);
        unpack2(acc[ch][1], lo1, hi1);
        dst[0] = make_float4(lo0, hi0, lo1, hi1);
        unpack2(acc[ch][2], lo0, hi0);
        unpack2(acc[ch][3], lo1, hi1);
        dst[1] = make_float4(lo0, hi0, lo1, hi1);
    }
}

// ---------------------------------------------------------------------------
// Combine: 192 blocks x 256 threads, one float4 per thread.
// sigmoid(canvas + sum of 8 group partials) -> out, sq-err reduce, fused loss.
// ---------------------------------------------------------------------------
__global__ void __launch_bounds__(256) combine_kernel(
    const float* __restrict__ canvas,
    const float* __restrict__ target,
    const float* __restrict__ sigma,
    const float* __restrict__ alpha,
    float* __restrict__ out,
    int out_size)
{
    __shared__ float ws[8];
    __shared__ int lastflag;

    const int tid = threadIdx.x;
    const int i = blockIdx.x * 256 + tid;   // float4 index, 49152 total

    float4 sum = ((const float4*)canvas)[i];
    #pragma unroll
    for (int gidx = 0; gidx < NG; gidx++) {
        float4 p = ((const float4*)&g_part[gidx][0])[i];
        sum.x += p.x; sum.y += p.y; sum.z += p.z; sum.w += p.w;
    }
    float4 o;
    o.x = __fdividef(1.0f, 1.0f + __expf(-sum.x));
    o.y = __fdividef(1.0f, 1.0f + __expf(-sum.y));
    o.z = __fdividef(1.0f, 1.0f + __expf(-sum.z));
    o.w = __fdividef(1.0f, 1.0f + __expf(-sum.w));
    ((float4*)out)[i] = o;

    float4 tg = ((const float4*)target)[i];
    float dx = o.x - tg.x, dy2 = o.y - tg.y, dz = o.z - tg.z, dw = o.w - tg.w;
    float sq = fmaf(dx, dx, fmaf(dy2, dy2, fmaf(dz, dz, dw * dw)));

    #pragma unroll
    for (int o2 = 16; o2 > 0; o2 >>= 1)
        sq += __shfl_down_sync(0xffffffffu, sq, o2);
    if ((tid & 31) == 0) ws[tid >> 5] = sq;
    __syncthreads();
    if (tid == 0) {
        float t2 = 0.f;
        #pragma unroll
        for (int k = 0; k < 8; k++) t2 += ws[k];
        g_red[blockIdx.x] = t2;
        __threadfence();
        unsigned prev = atomicAdd(&g_done, 1u);
        lastflag = (prev == 191u) ? 1 : 0;
    }
    __syncthreads();

    if (lastflag) {
        __shared__ float sa[256], sb[256], sc2[256];
        float pa = (tid < 192) ? g_red[tid] : 0.0f;
        float pb = 0.f, pc = 0.f;
        #pragma unroll
        for (int k = 0; k < 2; k++) {
            int nn = tid + 256 * k;
            pb += fabsf(1.0f - __fdividef(sigma[2 * nn], sigma[2 * nn + 1]));
            pc += fabsf(alpha[nn]);
        }
        sa[tid] = pa; sb[tid] = pb; sc2[tid] = pc;
        __syncthreads();
        for (int s2 = 128; s2 > 0; s2 >>= 1) {
            if (tid < s2) {
                sa[tid] += sa[tid + s2];
                sb[tid] += sb[tid + s2];
                sc2[tid] += sc2[tid + s2];
            }
            __syncthreads();
        }
        if (tid == 0) {
            float mse = sa[0] / (float)(3 * HW);
            float sharp = sb[0] * (0.001f / (float)NS);
            float transp = -sc2[0] * (0.001f / (float)NS);
            float psnr = -10.0f * log10f(mse + 1e-12f);
            float loss = mse + transp + sharp - psnr / 30.0f;
            if (out_size > 3 * HW) out[3 * HW] = loss;
        }
    }
}

// ---------------------------------------------------------------------------
extern "C" void kernel_launch(void* const* d_in, const int* in_sizes, int n_in,
                              void* d_out, int out_size)
{
    const float* canvas = (const float*)d_in[0];
    const float* target = (const float*)d_in[1];
    const float* offset = (const float*)d_in[2];
    const float* sigma  = (const float*)d_in[3];
    const float* theta  = (const float*)d_in[4];
    const float* color  = (const float*)d_in[5];
    const float* alpha  = (const float*)d_in[6];
    float* out = (float*)d_out;

    pass1_kernel<<<2, 256>>>(offset, sigma, theta, color, alpha);
    pass2_kernel<<<HH * NG, 32>>>();
    combine_kernel<<<192, 256>>>(canvas, target, sigma, alpha, out, out_size);
}